// round 16
// baseline (speedup 1.0000x reference)
#include <cuda_runtime.h>

// DynamicPatching: B=32, C=64, T=8192, S=64.
// out[b][s][c][p] = (p < len_bs) ? tensor[b][c][start_bs + p] : 0
// Output (B, S, C, max_len) row-major.
//
// R14 shared-alignment champion (warp owns rows {c, c+8, c+16, c+24}, which
// share one output alignment class -> warp-scalar p0/nv and k-step masks
// shared across all 4 rows; two-phase 16-load batch -> 4 STG.128) with
// __launch_bounds__(256, 8): regs capped at 32 for 8 CTAs/SM. The R14 loop
// carries little live state, so the squeeze costs ALU we have headroom for
// (issue 19%), buying the occupancy that covers the remaining DRAM latency.

#define PB 32
#define PC 64
#define PT 8192
#define PS 64

__device__ __forceinline__ void stcs4(float* p, float4 v) {
    asm volatile("st.global.cs.v4.f32 [%0], {%1,%2,%3,%4};"
                 :: "l"(p), "f"(v.x), "f"(v.y), "f"(v.z), "f"(v.w) : "memory");
}
__device__ __forceinline__ void stcs1(float* p, float v) {
    asm volatile("st.global.cs.f32 [%0], %1;" :: "l"(p), "f"(v) : "memory");
}

__global__ void __launch_bounds__(256, 8)
dynamic_patching_kernel(const float* __restrict__ tensor,
                        const int*   __restrict__ cps,   // (B, S+1) int32
                        float*       __restrict__ out,
                        int max_len)
{
    // 2 blocks per (b,s): each covers 32 of the 64 channels.
    const int bs   = blockIdx.x >> 1;
    const int half = blockIdx.x & 1;
    const int b    = bs >> 6;            // / PS
    const int s    = bs & (PS - 1);      // % PS

    const int start = __ldg(cps + b * (PS + 1) + s);
    const int len   = __ldg(cps + b * (PS + 1) + s + 1) - start;

    const int wid  = threadIdx.x >> 5;   // 0..7
    const int lane = threadIdx.x & 31;

    // Warp owns rows c0, c0+8, c0+16, c0+24 (same alignment class).
    const int c0 = half * 32 + wid;

    const float* __restrict__ src0 = tensor + ((b * PC + c0) << 13) + start;
    const int dbase = (bs * PC + c0) * max_len;      // fits int32 (< 2^25)
    float* __restrict__ dst0 = out + dbase;

    const int rs_src = 8 << 13;          // 8 channels of src stride (floats)
    const int rs_dst = 8 * max_len;      // 8 rows of dst stride (floats)

    // Warp-uniform alignment: all 4 rows share p0 / nv.
    const int p0 = (4 - (dbase & 3)) & 3;
    const int nv = (max_len - p0) >> 2;

    // Heads (< p0) and tails (< 4), hoisted. Shared p0/nv across rows.
    #pragma unroll
    for (int r = 0; r < 4; ++r) {
        const float* sr = src0 + r * rs_src;
        float*       dr = dst0 + r * rs_dst;
        if (lane < p0)
            stcs1(dr + lane, (lane < len) ? sr[lane] : 0.0f);
        const int p = p0 + (nv << 2) + lane;
        if (p < max_len)
            stcs1(dr + p, (p < len) ? sr[p] : 0.0f);
    }

    // Hot loop: two-phase. Masks m0..m3 computed ONCE per k-step and shared
    // by all 4 rows' loads. Phase 1: 16 independent predicated loads.
    // Phase 2: 4 STG.128.
    for (int kb = 0; kb < nv; kb += 32) {
        const int k = kb + lane;
        if (k < nv) {
            const int p  = p0 + (k << 2);
            const bool m0 = (p + 0) < len;
            const bool m1 = (p + 1) < len;
            const bool m2 = (p + 2) < len;
            const bool m3 = (p + 3) < len;

            float4 v[4];
            #pragma unroll
            for (int r = 0; r < 4; ++r) {
                const float* sp = src0 + r * rs_src + p;
                v[r] = make_float4(0.0f, 0.0f, 0.0f, 0.0f);
                if (m0) v[r].x = sp[0];
                if (m1) v[r].y = sp[1];
                if (m2) v[r].z = sp[2];
                if (m3) v[r].w = sp[3];
            }
            #pragma unroll
            for (int r = 0; r < 4; ++r)
                stcs4(dst0 + r * rs_dst + p, v[r]);
        }
    }
}

extern "C" void kernel_launch(void* const* d_in, const int* in_sizes, int n_in,
                              void* d_out, int out_size)
{
    const float* tensor = (const float*)d_in[0];
    const int*   cps    = (const int*)d_in[1];
    float*       out    = (float*)d_out;

    const int max_len = out_size / (PB * PS * PC);

    dynamic_patching_kernel<<<PB * PS * 2, 256>>>(tensor, cps, out, max_len);
}